// round 13
// baseline (speedup 1.0000x reference)
#include <cuda_runtime.h>
#include <cuda_bf16.h>
#include <math.h>
#include <stdint.h>

#define D    1024
#define E    8
#define HID  4096
#define NMAX 2048

// ---------------- device scratch (static globals: allowed) ----------------
__device__ __nv_bfloat16 g_Xhi[NMAX * D];
__device__ __nv_bfloat16 g_Xlo[NMAX * D];
__device__ __nv_bfloat16 g_W1hi[E * D * HID];
__device__ __nv_bfloat16 g_W1lo[E * D * HID];
__device__ __nv_bfloat16 g_W2hi[E * HID * D];
__device__ __nv_bfloat16 g_W2lo[E * HID * D];
__device__ __nv_bfloat16 g_Hhi[2 * NMAX * HID];
__device__ __nv_bfloat16 g_Hlo[2 * NMAX * HID];
__device__ int   g_cnt[E];      // zeroed by finalize (self-cleaning) + static zero
__device__ int   g_offs[E];
__device__ int   g_list[E * NMAX];   // packed-slot -> token
__device__ float g_wrow[E * NMAX];   // packed-slot -> combine weight
__device__ float g_imp[E];
__device__ float g_lse2;

// ---------------- helpers ----------------
__device__ __forceinline__ uint32_t smem_u32(const void* p) {
    uint32_t a;
    asm("{ .reg .u64 t; cvta.to.shared.u64 t, %1; cvt.u32.u64 %0, t; }"
        : "=r"(a) : "l"(p));
    return a;
}

__device__ __forceinline__ void cpasync16(uint32_t dst, const void* src, uint32_t bytes) {
    asm volatile("cp.async.cg.shared.global [%0], [%1], 16, %2;"
                 :: "r"(dst), "l"(src), "r"(bytes));
}
#define CP_COMMIT() asm volatile("cp.async.commit_group;")
#define CP_WAITG1() asm volatile("cp.async.wait_group 1;")

__device__ __forceinline__ void ldsm4(uint32_t* r, uint32_t addr) {
    asm volatile("ldmatrix.sync.aligned.m8n8.x4.shared.b16 {%0,%1,%2,%3}, [%4];"
                 : "=r"(r[0]), "=r"(r[1]), "=r"(r[2]), "=r"(r[3]) : "r"(addr));
}
__device__ __forceinline__ void ldsm4t(uint32_t* r, uint32_t addr) {
    asm volatile("ldmatrix.sync.aligned.m8n8.x4.trans.shared.b16 {%0,%1,%2,%3}, [%4];"
                 : "=r"(r[0]), "=r"(r[1]), "=r"(r[2]), "=r"(r[3]) : "r"(addr));
}
__device__ __forceinline__ void mma_bf16(float* c, const uint32_t* a, const uint32_t* b) {
    asm volatile(
        "mma.sync.aligned.m16n8k16.row.col.f32.bf16.bf16.f32 "
        "{%0,%1,%2,%3}, {%4,%5,%6,%7}, {%8,%9}, {%0,%1,%2,%3};"
        : "+f"(c[0]), "+f"(c[1]), "+f"(c[2]), "+f"(c[3])
        : "r"(a[0]), "r"(a[1]), "r"(a[2]), "r"(a[3]), "r"(b[0]), "r"(b[1]));
}

__device__ __forceinline__ float gelu_tanh(float v) {
    const float c = 0.7978845608028654f;
    float t = tanhf(c * (v + 0.044715f * v * v * v));
    return 0.5f * v * (1.0f + t);
}

__device__ __forceinline__ void split2u(float v0, float v1, uint32_t& hi, uint32_t& lo) {
    __nv_bfloat162 h = __floats2bfloat162_rn(v0, v1);
    float r0 = v0 - __bfloat162float(h.x);
    float r1 = v1 - __bfloat162float(h.y);
    __nv_bfloat162 l = __floats2bfloat162_rn(r0, r1);
    hi = *reinterpret_cast<uint32_t*>(&h);
    lo = *reinterpret_cast<uint32_t*>(&l);
}

// ---------------- presplit kernels ----------------
#define C4W (E * D * HID / 4)
#define C4X (NMAX * D / 4)

// W1 + X split (feeds ffn1; main stream)
__global__ void split_w1x(const float* __restrict__ W1,
                          const float* __restrict__ x) {
    long long i = (long long)blockIdx.x * blockDim.x + threadIdx.x;
    const float* src;
    __nv_bfloat16 *dhi, *dlo;
    long long j;
    if (i < C4W)            { src = W1; dhi = g_W1hi; dlo = g_W1lo; j = i; }
    else if (i < C4W + C4X) { src = x;  dhi = g_Xhi;  dlo = g_Xlo;  j = i - C4W; }
    else return;
    float4 v = ((const float4*)src)[j];
    uint2 h, l;
    split2u(v.x, v.y, h.x, l.x);
    split2u(v.z, v.w, h.y, l.y);
    ((uint2*)dhi)[j] = h;
    ((uint2*)dlo)[j] = l;
}

// W2 split (side stream, overlapped with ffn1)
__global__ void split_w2(const float* __restrict__ W2) {
    long long i = (long long)blockIdx.x * blockDim.x + threadIdx.x;
    if (i >= C4W) return;
    float4 v = ((const float4*)W2)[i];
    uint2 h, l;
    split2u(v.x, v.y, h.x, l.x);
    split2u(v.z, v.w, h.y, l.y);
    ((uint2*)g_W2hi)[i] = h;
    ((uint2*)g_W2lo)[i] = l;
}

// ---------------- router (also zeroes the out accumulation region) ----------------
// grid: N/8 blocks x 256 threads. Counters are pre-zeroed (static init on first
// call; finalize_kernel re-zeroes at the end of every call -> deterministic).
__global__ void router_kernel(const float* __restrict__ x,
                              const float* __restrict__ Wr,
                              const float* __restrict__ br, int N,
                              float* __restrict__ out) {
    // zero out[0 .. N*D) cooperatively: grid-stride float4
    {
        long long nt = (long long)gridDim.x * blockDim.x;
        long long items = (long long)N * D / 4;
        for (long long i = (long long)blockIdx.x * blockDim.x + threadIdx.x;
             i < items; i += nt)
            ((float4*)out)[i] = make_float4(0.f, 0.f, 0.f, 0.f);
    }

    int gwarp = (blockIdx.x * blockDim.x + threadIdx.x) >> 5;
    int lane  = threadIdx.x & 31;
    if (gwarp >= N) return;
    int t = gwarp;
    const float* xr = x + (size_t)t * D;

    float acc[E];
#pragma unroll
    for (int e = 0; e < E; e++) acc[e] = 0.0f;
    for (int d = lane; d < D; d += 32) {
        float xv = xr[d];
        const float4* w4 = (const float4*)(Wr + (size_t)d * E);
        float4 wa = w4[0], wb = w4[1];
        acc[0] += xv * wa.x; acc[1] += xv * wa.y;
        acc[2] += xv * wa.z; acc[3] += xv * wa.w;
        acc[4] += xv * wb.x; acc[5] += xv * wb.y;
        acc[6] += xv * wb.z; acc[7] += xv * wb.w;
    }
#pragma unroll
    for (int e = 0; e < E; e++) {
#pragma unroll
        for (int off = 16; off; off >>= 1)
            acc[e] += __shfl_down_sync(0xffffffffu, acc[e], off);
    }

    if (lane == 0) {
        float l[E];
#pragma unroll
        for (int e = 0; e < E; e++) l[e] = acc[e] + br[e];
        float m = l[0];
#pragma unroll
        for (int e = 1; e < E; e++) m = fmaxf(m, l[e]);
        float p[E]; float s = 0.0f;
#pragma unroll
        for (int e = 0; e < E; e++) { p[e] = expf(l[e] - m); s += p[e]; }
        float inv = 1.0f / s;
        float lse = m + logf(s);
        atomicAdd(&g_lse2, lse * lse);

        int i0 = 0, i1 = 0; float p0 = -1.0f, p1 = -1.0f;
#pragma unroll
        for (int e = 0; e < E; e++) {
            float pe = p[e] * inv;
            atomicAdd(&g_imp[e], pe);
            if (pe > p0)      { p1 = p0; i1 = i0; p0 = pe; i0 = e; }
            else if (pe > p1) { p1 = pe; i1 = e; }
        }
        float wsum = p0 + p1 + 1e-12f;
        float w0 = p0 / wsum, w1 = p1 / wsum;
        int pos0 = atomicAdd(&g_cnt[i0], 1);
        int pos1 = atomicAdd(&g_cnt[i1], 1);
        g_list[i0 * NMAX + pos0] = t;  g_wrow[i0 * NMAX + pos0] = w0;
        g_list[i1 * NMAX + pos1] = t;  g_wrow[i1 * NMAX + pos1] = w1;
    }
}

__global__ void scan_kernel() {
    if (threadIdx.x == 0) {
        int o = 0;
        for (int e = 0; e < E; e++) { g_offs[e] = o; o += g_cnt[e]; }
    }
}

// ---------------- mma.sync GEMM ----------------
// Tile: 128(M) x 128(N), BK=32, split-bf16 (hi/lo), 3-MMA per term-pair.
// 256 threads = 8 warps, warp tile 32x64 (4 warps M x 2 warps N).
// 3-stage cp.async ring, ONE __syncthreads per chunk, issue BEFORE compute.
// 113.7KB smem -> 2 CTAs/SM.
#define A_LD_B   80      // A row pitch bytes (40 bf16)
#define B_LD_B   272     // B row pitch bytes (136 bf16)
#define A_REG_SZ 10240   // 128*80
#define B_REG_SZ 8704    // 32*272
#define STAGE_BYTES (2*A_REG_SZ + 2*B_REG_SZ)   // 37888
#define SMEM_TOTAL  (3 * STAGE_BYTES)           // 113664

template<int PHASE>
__global__ __launch_bounds__(256, 2) void ffn_mma(
    const __nv_bfloat16* __restrict__ Whi,
    const __nv_bfloat16* __restrict__ Wlo,
    const float* __restrict__ bias,
    float* __restrict__ out)
{
    constexpr int KDIM = (PHASE == 1) ? D : HID;
    constexpr int NDIM = (PHASE == 1) ? HID : D;
    constexpr int NCH  = KDIM / 32;

    int e = blockIdx.z;
    int n = g_cnt[e];
    int r0 = blockIdx.y * 128;
    if (r0 >= n) return;
    int c0 = blockIdx.x * 128;
    int base = g_offs[e];

    extern __shared__ char smem[];
    uint32_t sb = smem_u32(smem);
    int t = threadIdx.x;
    int lane = t & 31, wid = t >> 5;

    // ---- per-thread cp.async source/dst setup ----
    int arow0 = t >> 2;
    const char* asrc[2][2];   // [hl][rowhalf]
    uint32_t abytes[2];
#pragma unroll
    for (int half = 0; half < 2; half++) {
        int rowg = r0 + arow0 + 64 * half;
        bool valid = rowg < n;
        size_t off;
        if (PHASE == 1) {
            int tok = valid ? g_list[e * NMAX + rowg] : 0;
            off = (size_t)tok * D + (t & 3) * 8;
            asrc[0][half] = (const char*)(g_Xhi + off);
            asrc[1][half] = (const char*)(g_Xlo + off);
        } else {
            int rr = valid ? rowg : 0;
            off = (size_t)(base + rr) * HID + (t & 3) * 8;
            asrc[0][half] = (const char*)(g_Hhi + off);
            asrc[1][half] = (const char*)(g_Hlo + off);
        }
        abytes[half] = valid ? 16u : 0u;
    }
    uint32_t adst0 = (uint32_t)(arow0 * A_LD_B + (t & 3) * 16);
    uint32_t adst1 = adst0 + 64 * A_LD_B;

    int bk0 = t >> 4;
    size_t wbase = (size_t)e * KDIM * NDIM + (size_t)bk0 * NDIM + c0 + (t & 15) * 8;
    const char* bsrc_h0 = (const char*)(Whi + wbase);
    const char* bsrc_h1 = (const char*)(Whi + wbase + (size_t)16 * NDIM);
    const char* bsrc_l0 = (const char*)(Wlo + wbase);
    const char* bsrc_l1 = (const char*)(Wlo + wbase + (size_t)16 * NDIM);
    uint32_t bdst0 = (uint32_t)(bk0 * B_LD_B + (t & 15) * 16);
    uint32_t bdst1 = bdst0 + 16 * B_LD_B;

    auto issue = [&](int kc, int stage) {
        uint32_t s0 = sb + stage * STAGE_BYTES;
        size_t aoff = (size_t)kc * 64;                 // 32 bf16 per chunk
        size_t boff = (size_t)kc * 32 * NDIM * 2;      // bytes
        cpasync16(s0 + adst0,               asrc[0][0] + aoff, abytes[0]);
        cpasync16(s0 + adst1,               asrc[0][1] + aoff, abytes[1]);
        cpasync16(s0 + A_REG_SZ + adst0,    asrc[1][0] + aoff, abytes[0]);
        cpasync16(s0 + A_REG_SZ + adst1,    asrc[1][1] + aoff, abytes[1]);
        uint32_t bb = s0 + 2 * A_REG_SZ;
        cpasync16(bb + bdst0,              bsrc_h0 + boff, 16);
        cpasync16(bb + bdst1,              bsrc_h1 + boff, 16);
        cpasync16(bb + B_REG_SZ + bdst0,   bsrc_l0 + boff, 16);
        cpasync16(bb + B_REG_SZ + bdst1,   bsrc_l1 + boff, 16);
    };

    // ---- per-warp ldmatrix lane offsets ----
    int m0  = (wid & 3) * 32;
    int n0w = (wid >> 2) * 64;
    uint32_t a_lane = (uint32_t)((m0 + (lane & 15)) * A_LD_B + (lane >> 4) * 16);
    uint32_t b_lane = (uint32_t)(((lane & 7) + 8 * ((lane >> 3) & 1)) * B_LD_B
                                 + (n0w + 8 * (lane >> 4)) * 2);

    float acc[2][8][4];
#pragma unroll
    for (int mt = 0; mt < 2; mt++)
#pragma unroll
        for (int nt = 0; nt < 8; nt++)
#pragma unroll
            for (int q = 0; q < 4; q++) acc[mt][nt][q] = 0.0f;

    // 3-stage prologue: 2 chunks in flight
    issue(0, 0); CP_COMMIT();
    issue(1, 1); CP_COMMIT();

    for (int kc = 0; kc < NCH; kc++) {
        CP_WAITG1();                     // this thread's chunk kc landed
        __syncthreads();                 // all landed; all warps done reading stage (kc-1)%3

        // issue NEXT chunk FIRST so its loads fly during compute(kc).
        // Writes stage (kc+2)%3 == (kc-1)%3 — safe past the barrier above.
        if (kc + 2 < NCH) issue(kc + 2, (kc + 2) % 3);
        CP_COMMIT();                     // unconditional: uniform group count

        uint32_t sA = sb + (kc % 3) * STAGE_BYTES;
        uint32_t sB = sA + 2 * A_REG_SZ;

#pragma unroll
        for (int ks = 0; ks < 2; ks++) {       // k sub-steps of 16
            uint32_t af[2][2][4];
#pragma unroll
            for (int hl = 0; hl < 2; hl++)
#pragma unroll
                for (int mt = 0; mt < 2; mt++)
                    ldsm4(af[hl][mt], sA + hl * A_REG_SZ + a_lane
                          + mt * 16 * A_LD_B + ks * 32);
#pragma unroll
            for (int g = 0; g < 4; g++) {      // n groups of 16 cols (2 nt each)
                uint32_t bh[4], bl[4];
                ldsm4t(bh, sB + b_lane + ks * 16 * B_LD_B + g * 32);
                ldsm4t(bl, sB + B_REG_SZ + b_lane + ks * 16 * B_LD_B + g * 32);
#pragma unroll
                for (int mt = 0; mt < 2; mt++) {
#pragma unroll
                    for (int sub = 0; sub < 2; sub++) {
                        float* a = acc[mt][g * 2 + sub];
                        mma_bf16(a, af[0][mt], &bh[sub * 2]);
                        mma_bf16(a, af[0][mt], &bl[sub * 2]);
                        mma_bf16(a, af[1][mt], &bh[sub * 2]);
                    }
                }
            }
        }
    }

    // ---- epilogue ----
    int lr = lane >> 2;
    int lc = (lane & 3) * 2;

    if (PHASE == 1) {
#pragma unroll
        for (int mt = 0; mt < 2; mt++) {
#pragma unroll
            for (int nt = 0; nt < 8; nt++) {
                int col = c0 + n0w + nt * 8 + lc;
                float bz0 = bias[e * NDIM + col];
                float bz1 = bias[e * NDIM + col + 1];
                int ra = r0 + m0 + mt * 16 + lr;
                int rb = ra + 8;
                float* a = acc[mt][nt];
                if (ra < n) {
                    float v0 = gelu_tanh(a[0] + bz0);
                    float v1 = gelu_tanh(a[1] + bz1);
                    uint32_t h, l; split2u(v0, v1, h, l);
                    size_t o = (size_t)(base + ra) * HID + col;
                    *(uint32_t*)(g_Hhi + o) = h;
                    *(uint32_t*)(g_Hlo + o) = l;
                }
                if (rb < n) {
                    float v0 = gelu_tanh(a[2] + bz0);
                    float v1 = gelu_tanh(a[3] + bz1);
                    uint32_t h, l; split2u(v0, v1, h, l);
                    size_t o = (size_t)(base + rb) * HID + col;
                    *(uint32_t*)(g_Hhi + o) = h;
                    *(uint32_t*)(g_Hlo + o) = l;
                }
            }
        }
    } else {
        // fused combine: out[token, col] += w * (acc + bias)
#pragma unroll
        for (int mt = 0; mt < 2; mt++) {
            int ra = r0 + m0 + mt * 16 + lr;
            int rb = ra + 8;
            int tokA = 0, tokB = 0; float wA = 0.f, wB = 0.f;
            if (ra < n) { tokA = g_list[e * NMAX + ra]; wA = g_wrow[e * NMAX + ra]; }
            if (rb < n) { tokB = g_list[e * NMAX + rb]; wB = g_wrow[e * NMAX + rb]; }
#pragma unroll
            for (int nt = 0; nt < 8; nt++) {
                int col = c0 + n0w + nt * 8 + lc;
                float bz0 = bias[e * NDIM + col];
                float bz1 = bias[e * NDIM + col + 1];
                float* a = acc[mt][nt];
                if (ra < n) {
                    atomicAdd(&out[(size_t)tokA * D + col],     wA * (a[0] + bz0));
                    atomicAdd(&out[(size_t)tokA * D + col + 1], wA * (a[1] + bz1));
                }
                if (rb < n) {
                    atomicAdd(&out[(size_t)tokB * D + col],     wB * (a[2] + bz0));
                    atomicAdd(&out[(size_t)tokB * D + col + 1], wB * (a[3] + bz1));
                }
            }
        }
    }
}

// ---------------- finalize (also self-cleans counters for next replay) ----------------
__global__ void finalize_kernel(float* __restrict__ out, int N, long long out_size) {
    if (threadIdx.x == 0) {
        float invN = 1.0f / (float)N;
        float z = g_lse2 * invN;
        float s = 0.0f;
        for (int e = 0; e < E; e++)
            s += (g_imp[e] * invN) * ((float)g_cnt[e] * invN);
        long long base = (long long)N * D;
        out[base]     = z;
        out[base + 1] = (float)E * s;
        for (long long i = base + 2; i < out_size; i++) out[i] = 0.0f;
        // self-clean for the next graph replay (deterministic: every call
        // starts from zeroed counters — statically zero on first call).
        g_lse2 = 0.0f;
        for (int e = 0; e < E; e++) { g_cnt[e] = 0; g_imp[e] = 0.0f; }
    }
}

extern "C" void kernel_launch(void* const* d_in, const int* in_sizes, int n_in,
                              void* d_out, int out_size) {
    const float* x  = (const float*)d_in[0];
    const float* Wr = (const float*)d_in[1];
    const float* br = (const float*)d_in[2];
    const float* W1 = (const float*)d_in[3];
    const float* b1 = (const float*)d_in[4];
    const float* W2 = (const float*)d_in[5];
    const float* b2 = (const float*)d_in[6];
    float* out = (float*)d_out;

    int N = in_sizes[0] / D;  // 2048

    void *p_w1hi, *p_w1lo, *p_w2hi, *p_w2lo;
    cudaGetSymbolAddress(&p_w1hi, g_W1hi);
    cudaGetSymbolAddress(&p_w1lo, g_W1lo);
    cudaGetSymbolAddress(&p_w2hi, g_W2hi);
    cudaGetSymbolAddress(&p_w2lo, g_W2lo);

    cudaFuncSetAttribute(ffn_mma<1>, cudaFuncAttributeMaxDynamicSharedMemorySize, SMEM_TOTAL);
    cudaFuncSetAttribute(ffn_mma<2>, cudaFuncAttributeMaxDynamicSharedMemorySize, SMEM_TOTAL);

    // side stream + events (created per call; not destroyed — capture-safe)
    cudaStream_t s2;
    cudaEvent_t evFork, evRoute, evW2;
    cudaStreamCreateWithFlags(&s2, cudaStreamNonBlocking);
    cudaEventCreateWithFlags(&evFork,  cudaEventDisableTiming);
    cudaEventCreateWithFlags(&evRoute, cudaEventDisableTiming);
    cudaEventCreateWithFlags(&evW2,    cudaEventDisableTiming);

    cudaEventRecord(evFork, 0);
    cudaStreamWaitEvent(s2, evFork, 0);

    // launch #1 (main): W1 + X split
    {
        long long items = (long long)C4W + C4X;
        split_w1x<<<(int)((items + 255) / 256), 256>>>(W1, x);
    }
    // launch #2 (s2): router (+ zero out region)
    {
        int warps_per_block = 8;
        int blocks = (N + warps_per_block - 1) / warps_per_block;
        router_kernel<<<blocks, warps_per_block * 32, 0, s2>>>(x, Wr, br, N, out);
    }
    // launch #3 (s2): scan
    scan_kernel<<<1, 1, 0, s2>>>();
    cudaEventRecord(evRoute, s2);

    // launch #4 (main): ffn1  <-- ncu capture slot
    cudaStreamWaitEvent(0, evRoute, 0);
    {
        dim3 grid(HID / 128, NMAX / 128, E);   // 32 x 16 x 8
        ffn_mma<1><<<grid, 256, SMEM_TOTAL>>>((const __nv_bfloat16*)p_w1hi,
                                              (const __nv_bfloat16*)p_w1lo, b1, out);
    }
    // launch #5 (s2): W2 split — concurrent with ffn1
    split_w2<<<(C4W + 255) / 256, 256, 0, s2>>>(W2);
    cudaEventRecord(evW2, s2);

    // launch #6 (main): ffn2 (fused combine)
    cudaStreamWaitEvent(0, evW2, 0);
    {
        dim3 grid(D / 128, NMAX / 128, E);     // 8 x 16 x 8
        ffn_mma<2><<<grid, 256, SMEM_TOTAL>>>((const __nv_bfloat16*)p_w2hi,
                                              (const __nv_bfloat16*)p_w2lo, b2, out);
    }
    // launch #7 (main): finalize + self-clean
    finalize_kernel<<<1, 32>>>(out, N, (long long)out_size);
}

// round 14
// speedup vs baseline: 2.2914x; 2.2914x over previous
#include <cuda_runtime.h>
#include <cuda_fp16.h>
#include <math.h>
#include <stdint.h>

#define D    1024
#define E    8
#define HID  4096
#define NMAX 2048

// ---------------- device scratch (static globals: allowed) ----------------
__device__ __half g_Xhi[NMAX * D];
__device__ __half g_Xlo[NMAX * D];
__device__ __half g_W1h[E * D * HID];
__device__ __half g_W2h[E * HID * D];
__device__ __half g_Hhi[2 * NMAX * HID];
__device__ __half g_Hlo[2 * NMAX * HID];
__device__ int   g_cnt[E];
__device__ int   g_offs[E];
__device__ int   g_list[E * NMAX];   // packed-slot -> token
__device__ float g_wrow[E * NMAX];   // packed-slot -> combine weight
__device__ float g_imp[E];
__device__ float g_lse2;

// ---------------- helpers ----------------
__device__ __forceinline__ uint32_t smem_u32(const void* p) {
    uint32_t a;
    asm("{ .reg .u64 t; cvta.to.shared.u64 t, %1; cvt.u32.u64 %0, t; }"
        : "=r"(a) : "l"(p));
    return a;
}

__device__ __forceinline__ void cpasync16(uint32_t dst, const void* src, uint32_t bytes) {
    asm volatile("cp.async.cg.shared.global [%0], [%1], 16, %2;"
                 :: "r"(dst), "l"(src), "r"(bytes));
}
#define CP_COMMIT() asm volatile("cp.async.commit_group;")
#define CP_WAITG1() asm volatile("cp.async.wait_group 1;")

__device__ __forceinline__ void ldsm4(uint32_t* r, uint32_t addr) {
    asm volatile("ldmatrix.sync.aligned.m8n8.x4.shared.b16 {%0,%1,%2,%3}, [%4];"
                 : "=r"(r[0]), "=r"(r[1]), "=r"(r[2]), "=r"(r[3]) : "r"(addr));
}
__device__ __forceinline__ void ldsm4t(uint32_t* r, uint32_t addr) {
    asm volatile("ldmatrix.sync.aligned.m8n8.x4.trans.shared.b16 {%0,%1,%2,%3}, [%4];"
                 : "=r"(r[0]), "=r"(r[1]), "=r"(r[2]), "=r"(r[3]) : "r"(addr));
}
__device__ __forceinline__ void mma_f16(float* c, const uint32_t* a, const uint32_t* b) {
    asm volatile(
        "mma.sync.aligned.m16n8k16.row.col.f32.f16.f16.f32 "
        "{%0,%1,%2,%3}, {%4,%5,%6,%7}, {%8,%9}, {%0,%1,%2,%3};"
        : "+f"(c[0]), "+f"(c[1]), "+f"(c[2]), "+f"(c[3])
        : "r"(a[0]), "r"(a[1]), "r"(a[2]), "r"(a[3]), "r"(b[0]), "r"(b[1]));
}

__device__ __forceinline__ float gelu_tanh(float v) {
    const float c = 0.7978845608028654f;
    float t = tanhf(c * (v + 0.044715f * v * v * v));
    return 0.5f * v * (1.0f + t);
}

// fp16 2-term split: v = hi + lo, |lo residual| ~ 2^-22 |v|
__device__ __forceinline__ void split2h(float v0, float v1, uint32_t& hi, uint32_t& lo) {
    __half2 h = __floats2half2_rn(v0, v1);
    float r0 = v0 - __half2float(__low2half(h));
    float r1 = v1 - __half2float(__high2half(h));
    __half2 l = __floats2half2_rn(r0, r1);
    hi = *reinterpret_cast<uint32_t*>(&h);
    lo = *reinterpret_cast<uint32_t*>(&l);
}

// ---------------- presplit kernels ----------------
#define C4W (E * D * HID / 4)
#define C4X (NMAX * D / 4)

// W1 (single fp16) + X (2-term fp16 split); main stream, feeds ffn1
__global__ void split_w1x(const float* __restrict__ W1,
                          const float* __restrict__ x) {
    long long i = (long long)blockIdx.x * blockDim.x + threadIdx.x;
    if (i < C4W) {
        float4 v = ((const float4*)W1)[i];
        __half2 a = __floats2half2_rn(v.x, v.y);
        __half2 b = __floats2half2_rn(v.z, v.w);
        ((uint2*)g_W1h)[i] = make_uint2(*reinterpret_cast<uint32_t*>(&a),
                                        *reinterpret_cast<uint32_t*>(&b));
    } else if (i < C4W + C4X) {
        long long j = i - C4W;
        float4 v = ((const float4*)x)[j];
        uint32_t h0, l0, h1, l1;
        split2h(v.x, v.y, h0, l0);
        split2h(v.z, v.w, h1, l1);
        ((uint2*)g_Xhi)[j] = make_uint2(h0, h1);
        ((uint2*)g_Xlo)[j] = make_uint2(l0, l1);
    }
}

// W2 (single fp16); side stream, overlapped with ffn1
__global__ void split_w2(const float* __restrict__ W2) {
    long long i = (long long)blockIdx.x * blockDim.x + threadIdx.x;
    if (i >= C4W) return;
    float4 v = ((const float4*)W2)[i];
    __half2 a = __floats2half2_rn(v.x, v.y);
    __half2 b = __floats2half2_rn(v.z, v.w);
    ((uint2*)g_W2h)[i] = make_uint2(*reinterpret_cast<uint32_t*>(&a),
                                    *reinterpret_cast<uint32_t*>(&b));
}

// zero d_out accumulation region + scalar init (precedes router on s2)
__global__ void zero_out_init(float* __restrict__ out) {
    long long i = (long long)blockIdx.x * blockDim.x + threadIdx.x;
    if (i == 0) {
        g_lse2 = 0.0f;
#pragma unroll
        for (int e = 0; e < E; e++) { g_cnt[e] = 0; g_imp[e] = 0.0f; }
    }
    if (i < (long long)NMAX * D / 4)
        ((float4*)out)[i] = make_float4(0.f, 0.f, 0.f, 0.f);
}

// ---------------- router ----------------
__global__ void router_kernel(const float* __restrict__ x,
                              const float* __restrict__ Wr,
                              const float* __restrict__ br, int N) {
    int gwarp = (blockIdx.x * blockDim.x + threadIdx.x) >> 5;
    int lane  = threadIdx.x & 31;
    if (gwarp >= N) return;
    int t = gwarp;
    const float* xr = x + (size_t)t * D;

    float acc[E];
#pragma unroll
    for (int e = 0; e < E; e++) acc[e] = 0.0f;
    for (int d = lane; d < D; d += 32) {
        float xv = xr[d];
        const float4* w4 = (const float4*)(Wr + (size_t)d * E);
        float4 wa = w4[0], wb = w4[1];
        acc[0] += xv * wa.x; acc[1] += xv * wa.y;
        acc[2] += xv * wa.z; acc[3] += xv * wa.w;
        acc[4] += xv * wb.x; acc[5] += xv * wb.y;
        acc[6] += xv * wb.z; acc[7] += xv * wb.w;
    }
#pragma unroll
    for (int e = 0; e < E; e++) {
#pragma unroll
        for (int off = 16; off; off >>= 1)
            acc[e] += __shfl_down_sync(0xffffffffu, acc[e], off);
    }

    if (lane == 0) {
        float l[E];
#pragma unroll
        for (int e = 0; e < E; e++) l[e] = acc[e] + br[e];
        float m = l[0];
#pragma unroll
        for (int e = 1; e < E; e++) m = fmaxf(m, l[e]);
        float p[E]; float s = 0.0f;
#pragma unroll
        for (int e = 0; e < E; e++) { p[e] = expf(l[e] - m); s += p[e]; }
        float inv = 1.0f / s;
        float lse = m + logf(s);
        atomicAdd(&g_lse2, lse * lse);

        int i0 = 0, i1 = 0; float p0 = -1.0f, p1 = -1.0f;
#pragma unroll
        for (int e = 0; e < E; e++) {
            float pe = p[e] * inv;
            atomicAdd(&g_imp[e], pe);
            if (pe > p0)      { p1 = p0; i1 = i0; p0 = pe; i0 = e; }
            else if (pe > p1) { p1 = pe; i1 = e; }
        }
        float wsum = p0 + p1 + 1e-12f;
        float w0 = p0 / wsum, w1 = p1 / wsum;
        int pos0 = atomicAdd(&g_cnt[i0], 1);
        int pos1 = atomicAdd(&g_cnt[i1], 1);
        g_list[i0 * NMAX + pos0] = t;  g_wrow[i0 * NMAX + pos0] = w0;
        g_list[i1 * NMAX + pos1] = t;  g_wrow[i1 * NMAX + pos1] = w1;
    }
}

__global__ void scan_kernel() {
    if (threadIdx.x == 0) {
        int o = 0;
        for (int e = 0; e < E; e++) { g_offs[e] = o; o += g_cnt[e]; }
    }
}

// ---------------- mma.sync GEMM (fp16, 2-term A split, single-fp16 B) ----------------
// Tile: 128(M) x 128(N), BK=32. 256 threads = 8 warps, warp tile 32x64.
// 3-stage cp.async ring, one barrier per chunk, issue AFTER compute (R12-proven).
// Stage: Ahi[128][40]f16 | Alo | Bh[32][136]f16 = 29184 B; x3 = 87552 -> 2 CTAs/SM.
#define A_LD_B   80      // A row pitch bytes (40 f16)
#define B_LD_B   272     // B row pitch bytes (136 f16)
#define A_REG_SZ 10240   // 128*80
#define B_REG_SZ 8704    // 32*272
#define STAGE_BYTES (2*A_REG_SZ + B_REG_SZ)   // 29184
#define SMEM_TOTAL  (3 * STAGE_BYTES)         // 87552

template<int PHASE>
__global__ __launch_bounds__(256, 2) void ffn_mma(
    const __half* __restrict__ Wh,
    const float* __restrict__ bias,
    float* __restrict__ out)
{
    constexpr int KDIM = (PHASE == 1) ? D : HID;
    constexpr int NDIM = (PHASE == 1) ? HID : D;
    constexpr int NCH  = KDIM / 32;

    int e = blockIdx.z;
    int n = g_cnt[e];
    int r0 = blockIdx.y * 128;
    if (r0 >= n) return;
    int c0 = blockIdx.x * 128;
    int base = g_offs[e];

    extern __shared__ char smem[];
    uint32_t sb = smem_u32(smem);
    int t = threadIdx.x;
    int lane = t & 31, wid = t >> 5;

    // ---- per-thread cp.async source/dst setup ----
    int arow0 = t >> 2;
    const char* asrc[2][2];   // [hl][rowhalf]
    uint32_t abytes[2];
#pragma unroll
    for (int half = 0; half < 2; half++) {
        int rowg = r0 + arow0 + 64 * half;
        bool valid = rowg < n;
        size_t off;
        if (PHASE == 1) {
            int tok = valid ? g_list[e * NMAX + rowg] : 0;
            off = (size_t)tok * D + (t & 3) * 8;
            asrc[0][half] = (const char*)(g_Xhi + off);
            asrc[1][half] = (const char*)(g_Xlo + off);
        } else {
            int rr = valid ? rowg : 0;
            off = (size_t)(base + rr) * HID + (t & 3) * 8;
            asrc[0][half] = (const char*)(g_Hhi + off);
            asrc[1][half] = (const char*)(g_Hlo + off);
        }
        abytes[half] = valid ? 16u : 0u;
    }
    uint32_t adst0 = (uint32_t)(arow0 * A_LD_B + (t & 3) * 16);
    uint32_t adst1 = adst0 + 64 * A_LD_B;

    int bk0 = t >> 4;
    size_t wbase = (size_t)e * KDIM * NDIM + (size_t)bk0 * NDIM + c0 + (t & 15) * 8;
    const char* bsrc_h0 = (const char*)(Wh + wbase);
    const char* bsrc_h1 = (const char*)(Wh + wbase + (size_t)16 * NDIM);
    uint32_t bdst0 = (uint32_t)(bk0 * B_LD_B + (t & 15) * 16);
    uint32_t bdst1 = bdst0 + 16 * B_LD_B;

    auto issue = [&](int kc, int stage) {
        uint32_t s0 = sb + stage * STAGE_BYTES;
        size_t aoff = (size_t)kc * 64;                 // 32 f16 per chunk
        size_t boff = (size_t)kc * 32 * NDIM * 2;      // bytes
        cpasync16(s0 + adst0,               asrc[0][0] + aoff, abytes[0]);
        cpasync16(s0 + adst1,               asrc[0][1] + aoff, abytes[1]);
        cpasync16(s0 + A_REG_SZ + adst0,    asrc[1][0] + aoff, abytes[0]);
        cpasync16(s0 + A_REG_SZ + adst1,    asrc[1][1] + aoff, abytes[1]);
        uint32_t bb = s0 + 2 * A_REG_SZ;
        cpasync16(bb + bdst0,              bsrc_h0 + boff, 16);
        cpasync16(bb + bdst1,              bsrc_h1 + boff, 16);
    };

    // ---- per-warp ldmatrix lane offsets ----
    int m0  = (wid & 3) * 32;
    int n0w = (wid >> 2) * 64;
    uint32_t a_lane = (uint32_t)((m0 + (lane & 15)) * A_LD_B + (lane >> 4) * 16);
    uint32_t b_lane = (uint32_t)(((lane & 7) + 8 * ((lane >> 3) & 1)) * B_LD_B
                                 + (n0w + 8 * (lane >> 4)) * 2);

    float acc[2][8][4];
#pragma unroll
    for (int mt = 0; mt < 2; mt++)
#pragma unroll
        for (int nt = 0; nt < 8; nt++)
#pragma unroll
            for (int q = 0; q < 4; q++) acc[mt][nt][q] = 0.0f;

    // 3-stage prologue: 2 chunks in flight
    issue(0, 0); CP_COMMIT();
    issue(1, 1); CP_COMMIT();

    for (int kc = 0; kc < NCH; kc++) {
        CP_WAITG1();                     // this thread's chunk kc landed
        __syncthreads();                 // all landed; all warps done reading (kc-1)%3

        uint32_t sA = sb + (kc % 3) * STAGE_BYTES;
        uint32_t sB = sA + 2 * A_REG_SZ;

#pragma unroll
        for (int ks = 0; ks < 2; ks++) {       // k sub-steps of 16
            uint32_t af[2][2][4];
#pragma unroll
            for (int hl = 0; hl < 2; hl++)
#pragma unroll
                for (int mt = 0; mt < 2; mt++)
                    ldsm4(af[hl][mt], sA + hl * A_REG_SZ + a_lane
                          + mt * 16 * A_LD_B + ks * 32);
#pragma unroll
            for (int g = 0; g < 4; g++) {      // n groups of 16 cols (2 nt each)
                uint32_t bh[4];
                ldsm4t(bh, sB + b_lane + ks * 16 * B_LD_B + g * 32);
#pragma unroll
                for (int mt = 0; mt < 2; mt++) {
#pragma unroll
                    for (int sub = 0; sub < 2; sub++) {
                        float* a = acc[mt][g * 2 + sub];
                        mma_f16(a, af[0][mt], &bh[sub * 2]);
                        mma_f16(a, af[1][mt], &bh[sub * 2]);
                    }
                }
            }
        }

        if (kc + 2 < NCH) issue(kc + 2, (kc + 2) % 3);   // AFTER compute (R12-proven)
        CP_COMMIT();                                     // uniform group count
    }

    // ---- epilogue ----
    int lr = lane >> 2;
    int lc = (lane & 3) * 2;

    if (PHASE == 1) {
#pragma unroll
        for (int mt = 0; mt < 2; mt++) {
#pragma unroll
            for (int nt = 0; nt < 8; nt++) {
                int col = c0 + n0w + nt * 8 + lc;
                float bz0 = bias[e * NDIM + col];
                float bz1 = bias[e * NDIM + col + 1];
                int ra = r0 + m0 + mt * 16 + lr;
                int rb = ra + 8;
                float* a = acc[mt][nt];
                if (ra < n) {
                    float v0 = gelu_tanh(a[0] + bz0);
                    float v1 = gelu_tanh(a[1] + bz1);
                    uint32_t h, l; split2h(v0, v1, h, l);
                    size_t o = (size_t)(base + ra) * HID + col;
                    *(uint32_t*)(g_Hhi + o) = h;
                    *(uint32_t*)(g_Hlo + o) = l;
                }
                if (rb < n) {
                    float v0 = gelu_tanh(a[2] + bz0);
                    float v1 = gelu_tanh(a[3] + bz1);
                    uint32_t h, l; split2h(v0, v1, h, l);
                    size_t o = (size_t)(base + rb) * HID + col;
                    *(uint32_t*)(g_Hhi + o) = h;
                    *(uint32_t*)(g_Hlo + o) = l;
                }
            }
        }
    } else {
        // fused combine: out[token, col] += w * (acc + bias)
#pragma unroll
        for (int mt = 0; mt < 2; mt++) {
            int ra = r0 + m0 + mt * 16 + lr;
            int rb = ra + 8;
            int tokA = 0, tokB = 0; float wA = 0.f, wB = 0.f;
            if (ra < n) { tokA = g_list[e * NMAX + ra]; wA = g_wrow[e * NMAX + ra]; }
            if (rb < n) { tokB = g_list[e * NMAX + rb]; wB = g_wrow[e * NMAX + rb]; }
#pragma unroll
            for (int nt = 0; nt < 8; nt++) {
                int col = c0 + n0w + nt * 8 + lc;
                float bz0 = bias[e * NDIM + col];
                float bz1 = bias[e * NDIM + col + 1];
                float* a = acc[mt][nt];
                if (ra < n) {
                    atomicAdd(&out[(size_t)tokA * D + col],     wA * (a[0] + bz0));
                    atomicAdd(&out[(size_t)tokA * D + col + 1], wA * (a[1] + bz1));
                }
                if (rb < n) {
                    atomicAdd(&out[(size_t)tokB * D + col],     wB * (a[2] + bz0));
                    atomicAdd(&out[(size_t)tokB * D + col + 1], wB * (a[3] + bz1));
                }
            }
        }
    }
}

// ---------------- finalize ----------------
__global__ void finalize_kernel(float* __restrict__ out, int N, long long out_size) {
    if (threadIdx.x == 0) {
        float invN = 1.0f / (float)N;
        float z = g_lse2 * invN;
        float s = 0.0f;
        for (int e = 0; e < E; e++)
            s += (g_imp[e] * invN) * ((float)g_cnt[e] * invN);
        long long base = (long long)N * D;
        out[base]     = z;
        out[base + 1] = (float)E * s;
        for (long long i = base + 2; i < out_size; i++) out[i] = 0.0f;
    }
}

extern "C" void kernel_launch(void* const* d_in, const int* in_sizes, int n_in,
                              void* d_out, int out_size) {
    const float* x  = (const float*)d_in[0];
    const float* Wr = (const float*)d_in[1];
    const float* br = (const float*)d_in[2];
    const float* W1 = (const float*)d_in[3];
    const float* b1 = (const float*)d_in[4];
    const float* W2 = (const float*)d_in[5];
    const float* b2 = (const float*)d_in[6];
    float* out = (float*)d_out;

    int N = in_sizes[0] / D;  // 2048

    void *p_w1h, *p_w2h;
    cudaGetSymbolAddress(&p_w1h, g_W1h);
    cudaGetSymbolAddress(&p_w2h, g_W2h);

    cudaFuncSetAttribute(ffn_mma<1>, cudaFuncAttributeMaxDynamicSharedMemorySize, SMEM_TOTAL);
    cudaFuncSetAttribute(ffn_mma<2>, cudaFuncAttributeMaxDynamicSharedMemorySize, SMEM_TOTAL);

    // side stream + events (created per call; not destroyed — capture-safe)
    cudaStream_t s2;
    cudaEvent_t evFork, evRoute, evW2;
    cudaStreamCreateWithFlags(&s2, cudaStreamNonBlocking);
    cudaEventCreateWithFlags(&evFork,  cudaEventDisableTiming);
    cudaEventCreateWithFlags(&evRoute, cudaEventDisableTiming);
    cudaEventCreateWithFlags(&evW2,    cudaEventDisableTiming);

    cudaEventRecord(evFork, 0);
    cudaStreamWaitEvent(s2, evFork, 0);

    // ---- side stream: init+zero, router, scan, then W2 convert ----
    {
        long long items = (long long)NMAX * D / 4;
        zero_out_init<<<(int)((items + 255) / 256), 256, 0, s2>>>(out);
    }
    {
        int warps_per_block = 8;
        int blocks = (N + warps_per_block - 1) / warps_per_block;
        router_kernel<<<blocks, warps_per_block * 32, 0, s2>>>(x, Wr, br, N);
    }
    scan_kernel<<<1, 1, 0, s2>>>();
    cudaEventRecord(evRoute, s2);
    split_w2<<<(C4W + 255) / 256, 256, 0, s2>>>(W2);
    cudaEventRecord(evW2, s2);

    // ---- main stream: W1+X convert (concurrent with router), then GEMMs ----
    {
        long long items = (long long)C4W + C4X;
        split_w1x<<<(int)((items + 255) / 256), 256>>>(W1, x);
    }
    cudaStreamWaitEvent(0, evRoute, 0);   // ffn1 needs router results
    {
        dim3 grid(HID / 128, NMAX / 128, E);   // 32 x 16 x 8
        ffn_mma<1><<<grid, 256, SMEM_TOTAL>>>((const __half*)p_w1h, b1, out);
    }
    cudaStreamWaitEvent(0, evW2, 0);      // ffn2 needs W2 convert + zeroed out
    {
        dim3 grid(D / 128, NMAX / 128, E);     // 8 x 16 x 8
        ffn_mma<2><<<grid, 256, SMEM_TOTAL>>>((const __half*)p_w2h, b2, out);
    }
    finalize_kernel<<<1, 32>>>(out, N, (long long)out_size);
}

// round 15
// speedup vs baseline: 2.3043x; 1.0057x over previous
#include <cuda_runtime.h>
#include <cuda_fp16.h>
#include <math.h>
#include <stdint.h>

#define D    1024
#define E    8
#define HID  4096
#define NMAX 2048

// ---------------- device scratch (static globals: allowed) ----------------
__device__ __half g_Xh[NMAX * D];
__device__ __half g_W1h[E * D * HID];
__device__ __half g_W2h[E * HID * D];
__device__ __half g_Hh[2 * NMAX * HID];
__device__ int   g_cnt[E];
__device__ int   g_offs[E];
__device__ int   g_list[E * NMAX];   // packed-slot -> token
__device__ float g_wrow[E * NMAX];   // packed-slot -> combine weight
__device__ float g_imp[E];
__device__ float g_lse2;

// ---------------- helpers ----------------
__device__ __forceinline__ uint32_t smem_u32(const void* p) {
    uint32_t a;
    asm("{ .reg .u64 t; cvta.to.shared.u64 t, %1; cvt.u32.u64 %0, t; }"
        : "=r"(a) : "l"(p));
    return a;
}

__device__ __forceinline__ void cpasync16(uint32_t dst, const void* src, uint32_t bytes) {
    asm volatile("cp.async.cg.shared.global [%0], [%1], 16, %2;"
                 :: "r"(dst), "l"(src), "r"(bytes));
}
#define CP_COMMIT() asm volatile("cp.async.commit_group;")
#define CP_WAITG1() asm volatile("cp.async.wait_group 1;")

__device__ __forceinline__ void ldsm4(uint32_t* r, uint32_t addr) {
    asm volatile("ldmatrix.sync.aligned.m8n8.x4.shared.b16 {%0,%1,%2,%3}, [%4];"
                 : "=r"(r[0]), "=r"(r[1]), "=r"(r[2]), "=r"(r[3]) : "r"(addr));
}
__device__ __forceinline__ void ldsm4t(uint32_t* r, uint32_t addr) {
    asm volatile("ldmatrix.sync.aligned.m8n8.x4.trans.shared.b16 {%0,%1,%2,%3}, [%4];"
                 : "=r"(r[0]), "=r"(r[1]), "=r"(r[2]), "=r"(r[3]) : "r"(addr));
}
__device__ __forceinline__ void mma_f16(float* c, const uint32_t* a, const uint32_t* b) {
    asm volatile(
        "mma.sync.aligned.m16n8k16.row.col.f32.f16.f16.f32 "
        "{%0,%1,%2,%3}, {%4,%5,%6,%7}, {%8,%9}, {%0,%1,%2,%3};"
        : "+f"(c[0]), "+f"(c[1]), "+f"(c[2]), "+f"(c[3])
        : "r"(a[0]), "r"(a[1]), "r"(a[2]), "r"(a[3]), "r"(b[0]), "r"(b[1]));
}

__device__ __forceinline__ float gelu_tanh(float v) {
    const float c = 0.7978845608028654f;
    float t = tanhf(c * (v + 0.044715f * v * v * v));
    return 0.5f * v * (1.0f + t);
}

// ---------------- presplit kernels ----------------
#define C4W (E * D * HID / 4)
#define C4X (NMAX * D / 4)

// W1 + X -> single fp16; main stream, feeds ffn1
__global__ void split_w1x(const float* __restrict__ W1,
                          const float* __restrict__ x) {
    long long i = (long long)blockIdx.x * blockDim.x + threadIdx.x;
    const float* src;
    __half* dst;
    long long j;
    if (i < C4W)            { src = W1; dst = g_W1h; j = i; }
    else if (i < C4W + C4X) { src = x;  dst = g_Xh;  j = i - C4W; }
    else return;
    float4 v = ((const float4*)src)[j];
    __half2 a = __floats2half2_rn(v.x, v.y);
    __half2 b = __floats2half2_rn(v.z, v.w);
    ((uint2*)dst)[j] = make_uint2(*reinterpret_cast<uint32_t*>(&a),
                                  *reinterpret_cast<uint32_t*>(&b));
}

// W2 -> single fp16; side stream, overlapped with ffn1
__global__ void split_w2(const float* __restrict__ W2) {
    long long i = (long long)blockIdx.x * blockDim.x + threadIdx.x;
    if (i >= C4W) return;
    float4 v = ((const float4*)W2)[i];
    __half2 a = __floats2half2_rn(v.x, v.y);
    __half2 b = __floats2half2_rn(v.z, v.w);
    ((uint2*)g_W2h)[i] = make_uint2(*reinterpret_cast<uint32_t*>(&a),
                                    *reinterpret_cast<uint32_t*>(&b));
}

// zero d_out accumulation region + scalar init (precedes router on s2)
__global__ void zero_out_init(float* __restrict__ out) {
    long long i = (long long)blockIdx.x * blockDim.x + threadIdx.x;
    if (i == 0) {
        g_lse2 = 0.0f;
#pragma unroll
        for (int e = 0; e < E; e++) { g_cnt[e] = 0; g_imp[e] = 0.0f; }
    }
    if (i < (long long)NMAX * D / 4)
        ((float4*)out)[i] = make_float4(0.f, 0.f, 0.f, 0.f);
}

// ---------------- router ----------------
__global__ void router_kernel(const float* __restrict__ x,
                              const float* __restrict__ Wr,
                              const float* __restrict__ br, int N) {
    int gwarp = (blockIdx.x * blockDim.x + threadIdx.x) >> 5;
    int lane  = threadIdx.x & 31;
    if (gwarp >= N) return;
    int t = gwarp;
    const float* xr = x + (size_t)t * D;

    float acc[E];
#pragma unroll
    for (int e = 0; e < E; e++) acc[e] = 0.0f;
    for (int d = lane; d < D; d += 32) {
        float xv = xr[d];
        const float4* w4 = (const float4*)(Wr + (size_t)d * E);
        float4 wa = w4[0], wb = w4[1];
        acc[0] += xv * wa.x; acc[1] += xv * wa.y;
        acc[2] += xv * wa.z; acc[3] += xv * wa.w;
        acc[4] += xv * wb.x; acc[5] += xv * wb.y;
        acc[6] += xv * wb.z; acc[7] += xv * wb.w;
    }
#pragma unroll
    for (int e = 0; e < E; e++) {
#pragma unroll
        for (int off = 16; off; off >>= 1)
            acc[e] += __shfl_down_sync(0xffffffffu, acc[e], off);
    }

    if (lane == 0) {
        float l[E];
#pragma unroll
        for (int e = 0; e < E; e++) l[e] = acc[e] + br[e];
        float m = l[0];
#pragma unroll
        for (int e = 1; e < E; e++) m = fmaxf(m, l[e]);
        float p[E]; float s = 0.0f;
#pragma unroll
        for (int e = 0; e < E; e++) { p[e] = expf(l[e] - m); s += p[e]; }
        float inv = 1.0f / s;
        float lse = m + logf(s);
        atomicAdd(&g_lse2, lse * lse);

        int i0 = 0, i1 = 0; float p0 = -1.0f, p1 = -1.0f;
#pragma unroll
        for (int e = 0; e < E; e++) {
            float pe = p[e] * inv;
            atomicAdd(&g_imp[e], pe);
            if (pe > p0)      { p1 = p0; i1 = i0; p0 = pe; i0 = e; }
            else if (pe > p1) { p1 = pe; i1 = e; }
        }
        float wsum = p0 + p1 + 1e-12f;
        float w0 = p0 / wsum, w1 = p1 / wsum;
        int pos0 = atomicAdd(&g_cnt[i0], 1);
        int pos1 = atomicAdd(&g_cnt[i1], 1);
        g_list[i0 * NMAX + pos0] = t;  g_wrow[i0 * NMAX + pos0] = w0;
        g_list[i1 * NMAX + pos1] = t;  g_wrow[i1 * NMAX + pos1] = w1;
    }
}

__global__ void scan_kernel() {
    if (threadIdx.x == 0) {
        int o = 0;
        for (int e = 0; e < E; e++) { g_offs[e] = o; o += g_cnt[e]; }
    }
}

// ---------------- mma.sync GEMM (single fp16 A and B, ONE MMA per tile) ----------------
// Tile: 128(M) x 128(N), BK=32. 256 threads = 8 warps, warp tile 32x64.
// 3-stage cp.async ring, one barrier per chunk, issue AFTER compute (proven).
// Stage: A[128][40]f16 | B[32][136]f16 = 18944 B; x3 = 56832 -> 2 CTAs/SM (reg-capped).
#define A_LD_B   80      // A row pitch bytes (40 f16)
#define B_LD_B   272     // B row pitch bytes (136 f16)
#define A_REG_SZ 10240   // 128*80
#define B_REG_SZ 8704    // 32*272
#define STAGE_BYTES (A_REG_SZ + B_REG_SZ)     // 18944
#define SMEM_TOTAL  (3 * STAGE_BYTES)         // 56832

template<int PHASE>
__global__ __launch_bounds__(256, 2) void ffn_mma(
    const __half* __restrict__ Wh,
    const float* __restrict__ bias,
    float* __restrict__ out)
{
    constexpr int KDIM = (PHASE == 1) ? D : HID;
    constexpr int NDIM = (PHASE == 1) ? HID : D;
    constexpr int NCH  = KDIM / 32;

    int e = blockIdx.z;
    int n = g_cnt[e];
    int r0 = blockIdx.y * 128;
    if (r0 >= n) return;
    int c0 = blockIdx.x * 128;
    int base = g_offs[e];

    extern __shared__ char smem[];
    uint32_t sb = smem_u32(smem);
    int t = threadIdx.x;
    int lane = t & 31, wid = t >> 5;

    // ---- per-thread cp.async source/dst setup ----
    int arow0 = t >> 2;
    const char* asrc[2];   // [rowhalf]
    uint32_t abytes[2];
#pragma unroll
    for (int half = 0; half < 2; half++) {
        int rowg = r0 + arow0 + 64 * half;
        bool valid = rowg < n;
        size_t off;
        if (PHASE == 1) {
            int tok = valid ? g_list[e * NMAX + rowg] : 0;
            off = (size_t)tok * D + (t & 3) * 8;
            asrc[half] = (const char*)(g_Xh + off);
        } else {
            int rr = valid ? rowg : 0;
            off = (size_t)(base + rr) * HID + (t & 3) * 8;
            asrc[half] = (const char*)(g_Hh + off);
        }
        abytes[half] = valid ? 16u : 0u;
    }
    uint32_t adst0 = (uint32_t)(arow0 * A_LD_B + (t & 3) * 16);
    uint32_t adst1 = adst0 + 64 * A_LD_B;

    int bk0 = t >> 4;
    size_t wbase = (size_t)e * KDIM * NDIM + (size_t)bk0 * NDIM + c0 + (t & 15) * 8;
    const char* bsrc_h0 = (const char*)(Wh + wbase);
    const char* bsrc_h1 = (const char*)(Wh + wbase + (size_t)16 * NDIM);
    uint32_t bdst0 = (uint32_t)(bk0 * B_LD_B + (t & 15) * 16);
    uint32_t bdst1 = bdst0 + 16 * B_LD_B;

    auto issue = [&](int kc, int stage) {
        uint32_t s0 = sb + stage * STAGE_BYTES;
        size_t aoff = (size_t)kc * 64;                 // 32 f16 per chunk
        size_t boff = (size_t)kc * 32 * NDIM * 2;      // bytes
        cpasync16(s0 + adst0,           asrc[0] + aoff, abytes[0]);
        cpasync16(s0 + adst1,           asrc[1] + aoff, abytes[1]);
        uint32_t bb = s0 + A_REG_SZ;
        cpasync16(bb + bdst0,           bsrc_h0 + boff, 16);
        cpasync16(bb + bdst1,           bsrc_h1 + boff, 16);
    };

    // ---- per-warp ldmatrix lane offsets ----
    int m0  = (wid & 3) * 32;
    int n0w = (wid >> 2) * 64;
    uint32_t a_lane = (uint32_t)((m0 + (lane & 15)) * A_LD_B + (lane >> 4) * 16);
    uint32_t b_lane = (uint32_t)(((lane & 7) + 8 * ((lane >> 3) & 1)) * B_LD_B
                                 + (n0w + 8 * (lane >> 4)) * 2);

    float acc[2][8][4];
#pragma unroll
    for (int mt = 0; mt < 2; mt++)
#pragma unroll
        for (int nt = 0; nt < 8; nt++)
#pragma unroll
            for (int q = 0; q < 4; q++) acc[mt][nt][q] = 0.0f;

    // 3-stage prologue: 2 chunks in flight
    issue(0, 0); CP_COMMIT();
    issue(1, 1); CP_COMMIT();

    for (int kc = 0; kc < NCH; kc++) {
        CP_WAITG1();                     // this thread's chunk kc landed
        __syncthreads();                 // all landed; all warps done reading (kc-1)%3

        uint32_t sA = sb + (kc % 3) * STAGE_BYTES;
        uint32_t sB = sA + A_REG_SZ;

#pragma unroll
        for (int ks = 0; ks < 2; ks++) {       // k sub-steps of 16
            uint32_t af[2][4];
#pragma unroll
            for (int mt = 0; mt < 2; mt++)
                ldsm4(af[mt], sA + a_lane + mt * 16 * A_LD_B + ks * 32);
#pragma unroll
            for (int g = 0; g < 4; g++) {      // n groups of 16 cols (2 nt each)
                uint32_t bh[4];
                ldsm4t(bh, sB + b_lane + ks * 16 * B_LD_B + g * 32);
#pragma unroll
                for (int mt = 0; mt < 2; mt++) {
#pragma unroll
                    for (int sub = 0; sub < 2; sub++) {
                        mma_f16(acc[mt][g * 2 + sub], af[mt], &bh[sub * 2]);
                    }
                }
            }
        }

        if (kc + 2 < NCH) issue(kc + 2, (kc + 2) % 3);   // AFTER compute (proven)
        CP_COMMIT();                                     // uniform group count
    }

    // ---- epilogue ----
    int lr = lane >> 2;
    int lc = (lane & 3) * 2;

    if (PHASE == 1) {
#pragma unroll
        for (int mt = 0; mt < 2; mt++) {
#pragma unroll
            for (int nt = 0; nt < 8; nt++) {
                int col = c0 + n0w + nt * 8 + lc;
                float bz0 = bias[e * NDIM + col];
                float bz1 = bias[e * NDIM + col + 1];
                int ra = r0 + m0 + mt * 16 + lr;
                int rb = ra + 8;
                float* a = acc[mt][nt];
                if (ra < n) {
                    float v0 = gelu_tanh(a[0] + bz0);
                    float v1 = gelu_tanh(a[1] + bz1);
                    __half2 h = __floats2half2_rn(v0, v1);
                    *(uint32_t*)(g_Hh + (size_t)(base + ra) * HID + col)
                        = *reinterpret_cast<uint32_t*>(&h);
                }
                if (rb < n) {
                    float v0 = gelu_tanh(a[2] + bz0);
                    float v1 = gelu_tanh(a[3] + bz1);
                    __half2 h = __floats2half2_rn(v0, v1);
                    *(uint32_t*)(g_Hh + (size_t)(base + rb) * HID + col)
                        = *reinterpret_cast<uint32_t*>(&h);
                }
            }
        }
    } else {
        // fused combine: out[token, col] += w * (acc + bias)
#pragma unroll
        for (int mt = 0; mt < 2; mt++) {
            int ra = r0 + m0 + mt * 16 + lr;
            int rb = ra + 8;
            int tokA = 0, tokB = 0; float wA = 0.f, wB = 0.f;
            if (ra < n) { tokA = g_list[e * NMAX + ra]; wA = g_wrow[e * NMAX + ra]; }
            if (rb < n) { tokB = g_list[e * NMAX + rb]; wB = g_wrow[e * NMAX + rb]; }
#pragma unroll
            for (int nt = 0; nt < 8; nt++) {
                int col = c0 + n0w + nt * 8 + lc;
                float bz0 = bias[e * NDIM + col];
                float bz1 = bias[e * NDIM + col + 1];
                float* a = acc[mt][nt];
                if (ra < n) {
                    atomicAdd(&out[(size_t)tokA * D + col],     wA * (a[0] + bz0));
                    atomicAdd(&out[(size_t)tokA * D + col + 1], wA * (a[1] + bz1));
                }
                if (rb < n) {
                    atomicAdd(&out[(size_t)tokB * D + col],     wB * (a[2] + bz0));
                    atomicAdd(&out[(size_t)tokB * D + col + 1], wB * (a[3] + bz1));
                }
            }
        }
    }
}

// ---------------- finalize ----------------
__global__ void finalize_kernel(float* __restrict__ out, int N, long long out_size) {
    if (threadIdx.x == 0) {
        float invN = 1.0f / (float)N;
        float z = g_lse2 * invN;
        float s = 0.0f;
        for (int e = 0; e < E; e++)
            s += (g_imp[e] * invN) * ((float)g_cnt[e] * invN);
        long long base = (long long)N * D;
        out[base]     = z;
        out[base + 1] = (float)E * s;
        for (long long i = base + 2; i < out_size; i++) out[i] = 0.0f;
    }
}

extern "C" void kernel_launch(void* const* d_in, const int* in_sizes, int n_in,
                              void* d_out, int out_size) {
    const float* x  = (const float*)d_in[0];
    const float* Wr = (const float*)d_in[1];
    const float* br = (const float*)d_in[2];
    const float* W1 = (const float*)d_in[3];
    const float* b1 = (const float*)d_in[4];
    const float* W2 = (const float*)d_in[5];
    const float* b2 = (const float*)d_in[6];
    float* out = (float*)d_out;

    int N = in_sizes[0] / D;  // 2048

    void *p_w1h, *p_w2h;
    cudaGetSymbolAddress(&p_w1h, g_W1h);
    cudaGetSymbolAddress(&p_w2h, g_W2h);

    cudaFuncSetAttribute(ffn_mma<1>, cudaFuncAttributeMaxDynamicSharedMemorySize, SMEM_TOTAL);
    cudaFuncSetAttribute(ffn_mma<2>, cudaFuncAttributeMaxDynamicSharedMemorySize, SMEM_TOTAL);

    // side stream + events (created per call; not destroyed — capture-safe)
    cudaStream_t s2;
    cudaEvent_t evFork, evRoute, evW2;
    cudaStreamCreateWithFlags(&s2, cudaStreamNonBlocking);
    cudaEventCreateWithFlags(&evFork,  cudaEventDisableTiming);
    cudaEventCreateWithFlags(&evRoute, cudaEventDisableTiming);
    cudaEventCreateWithFlags(&evW2,    cudaEventDisableTiming);

    cudaEventRecord(evFork, 0);
    cudaStreamWaitEvent(s2, evFork, 0);

    // ---- side stream: init+zero, router, scan, then W2 convert ----
    {
        long long items = (long long)NMAX * D / 4;
        zero_out_init<<<(int)((items + 255) / 256), 256, 0, s2>>>(out);
    }
    {
        int warps_per_block = 8;
        int blocks = (N + warps_per_block - 1) / warps_per_block;
        router_kernel<<<blocks, warps_per_block * 32, 0, s2>>>(x, Wr, br, N);
    }
    scan_kernel<<<1, 1, 0, s2>>>();
    cudaEventRecord(evRoute, s2);
    split_w2<<<(C4W + 255) / 256, 256, 0, s2>>>(W2);
    cudaEventRecord(evW2, s2);

    // ---- main stream: W1+X convert (concurrent with router), then GEMMs ----
    {
        long long items = (long long)C4W + C4X;
        split_w1x<<<(int)((items + 255) / 256), 256>>>(W1, x);
    }
    cudaStreamWaitEvent(0, evRoute, 0);   // ffn1 needs router results
    {
        dim3 grid(HID / 128, NMAX / 128, E);   // 32 x 16 x 8
        ffn_mma<1><<<grid, 256, SMEM_TOTAL>>>((const __half*)p_w1h, b1, out);
    }
    cudaStreamWaitEvent(0, evW2, 0);      // ffn2 needs W2 convert + zeroed out
    {
        dim3 grid(D / 128, NMAX / 128, E);     // 8 x 16 x 8
        ffn_mma<2><<<grid, 256, SMEM_TOTAL>>>((const __half*)p_w2h, b2, out);
    }
    finalize_kernel<<<1, 32>>>(out, N, (long long)out_size);
}

// round 16
// speedup vs baseline: 2.5214x; 1.0942x over previous
#include <cuda_runtime.h>
#include <cuda_fp16.h>
#include <math.h>
#include <stdint.h>

#define D    1024
#define E    8
#define HID  4096
#define NMAX 2048

// ---------------- device scratch (static globals: allowed) ----------------
__device__ __half g_Xh[NMAX * D];
__device__ __half g_W1h[E * D * HID];
__device__ __half g_W2h[E * HID * D];
__device__ __half g_Hh[2 * NMAX * HID];
__device__ int   g_cnt[E];      // zeroed statically + by finalize (R13-proven)
__device__ int   g_offs[E];
__device__ int   g_list[E * NMAX];   // packed-slot -> token
__device__ float g_wrow[E * NMAX];   // packed-slot -> combine weight
__device__ float g_imp[E];
__device__ float g_lse2;

// ---------------- helpers ----------------
__device__ __forceinline__ uint32_t smem_u32(const void* p) {
    uint32_t a;
    asm("{ .reg .u64 t; cvta.to.shared.u64 t, %1; cvt.u32.u64 %0, t; }"
        : "=r"(a) : "l"(p));
    return a;
}

__device__ __forceinline__ void cpasync16(uint32_t dst, const void* src, uint32_t bytes) {
    asm volatile("cp.async.cg.shared.global [%0], [%1], 16, %2;"
                 :: "r"(dst), "l"(src), "r"(bytes));
}
#define CP_COMMIT() asm volatile("cp.async.commit_group;")
#define CP_WAITG1() asm volatile("cp.async.wait_group 1;")

__device__ __forceinline__ void ldsm4(uint32_t* r, uint32_t addr) {
    asm volatile("ldmatrix.sync.aligned.m8n8.x4.shared.b16 {%0,%1,%2,%3}, [%4];"
                 : "=r"(r[0]), "=r"(r[1]), "=r"(r[2]), "=r"(r[3]) : "r"(addr));
}
__device__ __forceinline__ void ldsm4t(uint32_t* r, uint32_t addr) {
    asm volatile("ldmatrix.sync.aligned.m8n8.x4.trans.shared.b16 {%0,%1,%2,%3}, [%4];"
                 : "=r"(r[0]), "=r"(r[1]), "=r"(r[2]), "=r"(r[3]) : "r"(addr));
}
__device__ __forceinline__ void mma_f16(float* c, const uint32_t* a, const uint32_t* b) {
    asm volatile(
        "mma.sync.aligned.m16n8k16.row.col.f32.f16.f16.f32 "
        "{%0,%1,%2,%3}, {%4,%5,%6,%7}, {%8,%9}, {%0,%1,%2,%3};"
        : "+f"(c[0]), "+f"(c[1]), "+f"(c[2]), "+f"(c[3])
        : "r"(a[0]), "r"(a[1]), "r"(a[2]), "r"(a[3]), "r"(b[0]), "r"(b[1]));
}

__device__ __forceinline__ float gelu_tanh(float v) {
    const float c = 0.7978845608028654f;
    float t = tanhf(c * (v + 0.044715f * v * v * v));
    return 0.5f * v * (1.0f + t);
}

// ---------------- presplit kernels ----------------
#define C4W (E * D * HID / 4)
#define C4X (NMAX * D / 4)

// W1 + X -> single fp16; main stream, feeds ffn1   (launch #1)
__global__ void split_w1x(const float* __restrict__ W1,
                          const float* __restrict__ x) {
    long long i = (long long)blockIdx.x * blockDim.x + threadIdx.x;
    const float* src;
    __half* dst;
    long long j;
    if (i < C4W)            { src = W1; dst = g_W1h; j = i; }
    else if (i < C4W + C4X) { src = x;  dst = g_Xh;  j = i - C4W; }
    else return;
    float4 v = ((const float4*)src)[j];
    __half2 a = __floats2half2_rn(v.x, v.y);
    __half2 b = __floats2half2_rn(v.z, v.w);
    ((uint2*)dst)[j] = make_uint2(*reinterpret_cast<uint32_t*>(&a),
                                  *reinterpret_cast<uint32_t*>(&b));
}

// W2 -> single fp16; side stream, overlapped with ffn1   (launch #5)
__global__ void split_w2(const float* __restrict__ W2) {
    long long i = (long long)blockIdx.x * blockDim.x + threadIdx.x;
    if (i >= C4W) return;
    float4 v = ((const float4*)W2)[i];
    __half2 a = __floats2half2_rn(v.x, v.y);
    __half2 b = __floats2half2_rn(v.z, v.w);
    ((uint2*)g_W2h)[i] = make_uint2(*reinterpret_cast<uint32_t*>(&a),
                                    *reinterpret_cast<uint32_t*>(&b));
}

// ---------------- router (also zeroes the out accumulation region) -------- (launch #2)
__global__ void router_kernel(const float* __restrict__ x,
                              const float* __restrict__ Wr,
                              const float* __restrict__ br, int N,
                              float* __restrict__ out) {
    // zero out[0 .. N*D) cooperatively
    {
        long long nt = (long long)gridDim.x * blockDim.x;
        long long items = (long long)N * D / 4;
        for (long long i = (long long)blockIdx.x * blockDim.x + threadIdx.x;
             i < items; i += nt)
            ((float4*)out)[i] = make_float4(0.f, 0.f, 0.f, 0.f);
    }

    int gwarp = (blockIdx.x * blockDim.x + threadIdx.x) >> 5;
    int lane  = threadIdx.x & 31;
    if (gwarp >= N) return;
    int t = gwarp;
    const float* xr = x + (size_t)t * D;

    float acc[E];
#pragma unroll
    for (int e = 0; e < E; e++) acc[e] = 0.0f;
    for (int d = lane; d < D; d += 32) {
        float xv = xr[d];
        const float4* w4 = (const float4*)(Wr + (size_t)d * E);
        float4 wa = w4[0], wb = w4[1];
        acc[0] += xv * wa.x; acc[1] += xv * wa.y;
        acc[2] += xv * wa.z; acc[3] += xv * wa.w;
        acc[4] += xv * wb.x; acc[5] += xv * wb.y;
        acc[6] += xv * wb.z; acc[7] += xv * wb.w;
    }
#pragma unroll
    for (int e = 0; e < E; e++) {
#pragma unroll
        for (int off = 16; off; off >>= 1)
            acc[e] += __shfl_down_sync(0xffffffffu, acc[e], off);
    }

    if (lane == 0) {
        float l[E];
#pragma unroll
        for (int e = 0; e < E; e++) l[e] = acc[e] + br[e];
        float m = l[0];
#pragma unroll
        for (int e = 1; e < E; e++) m = fmaxf(m, l[e]);
        float p[E]; float s = 0.0f;
#pragma unroll
        for (int e = 0; e < E; e++) { p[e] = expf(l[e] - m); s += p[e]; }
        float inv = 1.0f / s;
        float lse = m + logf(s);
        atomicAdd(&g_lse2, lse * lse);

        int i0 = 0, i1 = 0; float p0 = -1.0f, p1 = -1.0f;
#pragma unroll
        for (int e = 0; e < E; e++) {
            float pe = p[e] * inv;
            atomicAdd(&g_imp[e], pe);
            if (pe > p0)      { p1 = p0; i1 = i0; p0 = pe; i0 = e; }
            else if (pe > p1) { p1 = pe; i1 = e; }
        }
        float wsum = p0 + p1 + 1e-12f;
        float w0 = p0 / wsum, w1 = p1 / wsum;
        int pos0 = atomicAdd(&g_cnt[i0], 1);
        int pos1 = atomicAdd(&g_cnt[i1], 1);
        g_list[i0 * NMAX + pos0] = t;  g_wrow[i0 * NMAX + pos0] = w0;
        g_list[i1 * NMAX + pos1] = t;  g_wrow[i1 * NMAX + pos1] = w1;
    }
}

__global__ void scan_kernel() {   // launch #3
    if (threadIdx.x == 0) {
        int o = 0;
        for (int e = 0; e < E; e++) { g_offs[e] = o; o += g_cnt[e]; }
    }
}

// ---------------- mma.sync GEMM (single fp16, BK=64, optional split-K) ----------------
// Tile: 128(M) x 128(N), BK=64. 256 threads = 8 warps, warp tile 32x64.
// 3-stage cp.async ring, one barrier per chunk, issue AFTER compute (proven).
// Stage: A[128][144B] + B[64][272B] = 35840 B; x3 = 107520 -> 2 CTAs/SM.
#define A_LD_B   144     // A row pitch bytes (64 f16 + 16B pad)
#define B_LD_B   272     // B row pitch bytes (128 f16 + 8 pad)
#define A_REG_SZ (128 * A_LD_B)   // 18432
#define B_REG_SZ (64 * B_LD_B)    // 17408
#define STAGE_BYTES (A_REG_SZ + B_REG_SZ)   // 35840
#define SMEM_TOTAL  (3 * STAGE_BYTES)       // 107520

template<int PHASE, int SPLITK>
__global__ __launch_bounds__(256, 2) void ffn_mma(
    const __half* __restrict__ Wh,
    const float* __restrict__ bias,
    float* __restrict__ out)
{
    constexpr int KDIM = (PHASE == 1) ? D : HID;
    constexpr int NDIM = (PHASE == 1) ? HID : D;
    constexpr int KSEG = KDIM / SPLITK;       // K range per split
    constexpr int NCH  = KSEG / 64;

    int e   = blockIdx.z / SPLITK;
    int ksp = blockIdx.z % SPLITK;
    int n = g_cnt[e];
    int r0 = blockIdx.y * 128;
    if (r0 >= n) return;
    int c0 = blockIdx.x * 128;
    int base = g_offs[e];
    size_t kbase = (size_t)ksp * KSEG;        // element offset in K

    extern __shared__ char smem[];
    uint32_t sb = smem_u32(smem);
    int t = threadIdx.x;
    int lane = t & 31, wid = t >> 5;

    // ---- A cp.async: row = t>>1 (2 threads/row), 4 x 16B each ----
    int arow = t >> 1;
    const char* asrc;
    uint32_t abytes;
    {
        int rowg = r0 + arow;
        bool valid = rowg < n;
        size_t off;
        if (PHASE == 1) {
            int tok = valid ? g_list[e * NMAX + rowg] : 0;
            off = (size_t)tok * D + kbase + (t & 1) * 32;
            asrc = (const char*)(g_Xh + off);
        } else {
            int rr = valid ? rowg : 0;
            off = (size_t)(base + rr) * HID + kbase + (t & 1) * 32;
            asrc = (const char*)(g_Hh + off);
        }
        abytes = valid ? 16u : 0u;
    }
    uint32_t adst = (uint32_t)(arow * A_LD_B + (t & 1) * 64);

    // ---- B cp.async: k-row = t>>2 (4 threads/row), 4 x 16B each ----
    int bk0 = t >> 2;
    size_t wbase = (size_t)e * KDIM * NDIM + (kbase + bk0) * NDIM + c0 + (t & 3) * 32;
    const char* bsrc = (const char*)(Wh + wbase);
    uint32_t bdst = (uint32_t)(bk0 * B_LD_B + (t & 3) * 64);

    auto issue = [&](int kc, int stage) {
        uint32_t s0 = sb + stage * STAGE_BYTES;
        size_t aoff = (size_t)kc * 128;                // 64 f16 = 128 bytes
        size_t boff = (size_t)kc * 64 * NDIM * 2;      // bytes
#pragma unroll
        for (int q = 0; q < 4; q++)
            cpasync16(s0 + adst + q * 16, asrc + aoff + q * 16, abytes);
        uint32_t bb = s0 + A_REG_SZ;
#pragma unroll
        for (int q = 0; q < 4; q++)
            cpasync16(bb + bdst + q * 16, bsrc + boff + q * 16, 16);
    };

    // ---- per-warp ldmatrix lane offsets ----
    int m0  = (wid & 3) * 32;
    int n0w = (wid >> 2) * 64;
    uint32_t a_lane = (uint32_t)((m0 + (lane & 15)) * A_LD_B + (lane >> 4) * 16);
    uint32_t b_lane = (uint32_t)(((lane & 7) + 8 * ((lane >> 3) & 1)) * B_LD_B
                                 + (n0w + 8 * (lane >> 4)) * 2);

    float acc[2][8][4];
#pragma unroll
    for (int mt = 0; mt < 2; mt++)
#pragma unroll
        for (int nt = 0; nt < 8; nt++)
#pragma unroll
            for (int q = 0; q < 4; q++) acc[mt][nt][q] = 0.0f;

    // 3-stage prologue: 2 chunks in flight
    issue(0, 0); CP_COMMIT();
    issue(1, 1); CP_COMMIT();

    for (int kc = 0; kc < NCH; kc++) {
        CP_WAITG1();                     // this thread's chunk kc landed
        __syncthreads();                 // all landed; all warps done reading (kc-1)%3

        uint32_t sA = sb + (kc % 3) * STAGE_BYTES;
        uint32_t sB = sA + A_REG_SZ;

#pragma unroll
        for (int ks = 0; ks < 4; ks++) {       // k sub-steps of 16 (BK=64)
            uint32_t af[2][4];
#pragma unroll
            for (int mt = 0; mt < 2; mt++)
                ldsm4(af[mt], sA + a_lane + mt * 16 * A_LD_B + ks * 32);
#pragma unroll
            for (int g = 0; g < 4; g++) {      // n groups of 16 cols (2 nt each)
                uint32_t bh[4];
                ldsm4t(bh, sB + b_lane + ks * 16 * B_LD_B + g * 32);
#pragma unroll
                for (int mt = 0; mt < 2; mt++) {
#pragma unroll
                    for (int sub = 0; sub < 2; sub++) {
                        mma_f16(acc[mt][g * 2 + sub], af[mt], &bh[sub * 2]);
                    }
                }
            }
        }

        if (kc + 2 < NCH) issue(kc + 2, (kc + 2) % 3);   // AFTER compute (proven)
        CP_COMMIT();                                     // uniform group count
    }

    // ---- epilogue ----
    int lr = lane >> 2;
    int lc = (lane & 3) * 2;

    if (PHASE == 1) {
#pragma unroll
        for (int mt = 0; mt < 2; mt++) {
#pragma unroll
            for (int nt = 0; nt < 8; nt++) {
                int col = c0 + n0w + nt * 8 + lc;
                float bz0 = bias[e * NDIM + col];
                float bz1 = bias[e * NDIM + col + 1];
                int ra = r0 + m0 + mt * 16 + lr;
                int rb = ra + 8;
                float* a = acc[mt][nt];
                if (ra < n) {
                    float v0 = gelu_tanh(a[0] + bz0);
                    float v1 = gelu_tanh(a[1] + bz1);
                    __half2 h = __floats2half2_rn(v0, v1);
                    *(uint32_t*)(g_Hh + (size_t)(base + ra) * HID + col)
                        = *reinterpret_cast<uint32_t*>(&h);
                }
                if (rb < n) {
                    float v0 = gelu_tanh(a[2] + bz0);
                    float v1 = gelu_tanh(a[3] + bz1);
                    __half2 h = __floats2half2_rn(v0, v1);
                    *(uint32_t*)(g_Hh + (size_t)(base + rb) * HID + col)
                        = *reinterpret_cast<uint32_t*>(&h);
                }
            }
        }
    } else {
        // fused combine: out[token, col] += w * (acc + bias); bias only from split 0
        float bscale = (ksp == 0) ? 1.0f : 0.0f;
#pragma unroll
        for (int mt = 0; mt < 2; mt++) {
            int ra = r0 + m0 + mt * 16 + lr;
            int rb = ra + 8;
            int tokA = 0, tokB = 0; float wA = 0.f, wB = 0.f;
            if (ra < n) { tokA = g_list[e * NMAX + ra]; wA = g_wrow[e * NMAX + ra]; }
            if (rb < n) { tokB = g_list[e * NMAX + rb]; wB = g_wrow[e * NMAX + rb]; }
#pragma unroll
            for (int nt = 0; nt < 8; nt++) {
                int col = c0 + n0w + nt * 8 + lc;
                float bz0 = bscale * bias[e * NDIM + col];
                float bz1 = bscale * bias[e * NDIM + col + 1];
                float* a = acc[mt][nt];
                if (ra < n) {
                    atomicAdd(&out[(size_t)tokA * D + col],     wA * (a[0] + bz0));
                    atomicAdd(&out[(size_t)tokA * D + col + 1], wA * (a[1] + bz1));
                }
                if (rb < n) {
                    atomicAdd(&out[(size_t)tokB * D + col],     wB * (a[2] + bz0));
                    atomicAdd(&out[(size_t)tokB * D + col + 1], wB * (a[3] + bz1));
                }
            }
        }
    }
}

// ---------------- finalize (self-cleans counters for next replay) ----------------
__global__ void finalize_kernel(float* __restrict__ out, int N, long long out_size) {
    if (threadIdx.x == 0) {
        float invN = 1.0f / (float)N;
        float z = g_lse2 * invN;
        float s = 0.0f;
        for (int e = 0; e < E; e++)
            s += (g_imp[e] * invN) * ((float)g_cnt[e] * invN);
        long long base = (long long)N * D;
        out[base]     = z;
        out[base + 1] = (float)E * s;
        for (long long i = base + 2; i < out_size; i++) out[i] = 0.0f;
        // self-clean (R13-proven): next replay starts from zeroed counters
        g_lse2 = 0.0f;
        for (int e = 0; e < E; e++) { g_cnt[e] = 0; g_imp[e] = 0.0f; }
    }
}

extern "C" void kernel_launch(void* const* d_in, const int* in_sizes, int n_in,
                              void* d_out, int out_size) {
    const float* x  = (const float*)d_in[0];
    const float* Wr = (const float*)d_in[1];
    const float* br = (const float*)d_in[2];
    const float* W1 = (const float*)d_in[3];
    const float* b1 = (const float*)d_in[4];
    const float* W2 = (const float*)d_in[5];
    const float* b2 = (const float*)d_in[6];
    float* out = (float*)d_out;

    int N = in_sizes[0] / D;  // 2048

    void *p_w1h, *p_w2h;
    cudaGetSymbolAddress(&p_w1h, g_W1h);
    cudaGetSymbolAddress(&p_w2h, g_W2h);

    cudaFuncSetAttribute(ffn_mma<1, 1>, cudaFuncAttributeMaxDynamicSharedMemorySize, SMEM_TOTAL);
    cudaFuncSetAttribute(ffn_mma<2, 4>, cudaFuncAttributeMaxDynamicSharedMemorySize, SMEM_TOTAL);

    // side stream + events (created per call; not destroyed — capture-safe)
    cudaStream_t s2;
    cudaEvent_t evFork, evRoute, evW2;
    cudaStreamCreateWithFlags(&s2, cudaStreamNonBlocking);
    cudaEventCreateWithFlags(&evFork,  cudaEventDisableTiming);
    cudaEventCreateWithFlags(&evRoute, cudaEventDisableTiming);
    cudaEventCreateWithFlags(&evW2,    cudaEventDisableTiming);

    cudaEventRecord(evFork, 0);
    cudaStreamWaitEvent(s2, evFork, 0);

    // launch #1 (main): W1 + X convert
    {
        long long items = (long long)C4W + C4X;
        split_w1x<<<(int)((items + 255) / 256), 256>>>(W1, x);
    }
    // launch #2 (s2): router (+ zero out region)
    {
        int warps_per_block = 8;
        int blocks = (N + warps_per_block - 1) / warps_per_block;
        router_kernel<<<blocks, warps_per_block * 32, 0, s2>>>(x, Wr, br, N, out);
    }
    // launch #3 (s2): scan
    scan_kernel<<<1, 1, 0, s2>>>();
    cudaEventRecord(evRoute, s2);

    // launch #4 (main): ffn1  <-- ncu capture slot
    cudaStreamWaitEvent(0, evRoute, 0);
    {
        dim3 grid(HID / 128, NMAX / 128, E);        // 32 x 16 x 8
        ffn_mma<1, 1><<<grid, 256, SMEM_TOTAL>>>((const __half*)p_w1h, b1, out);
    }
    // launch #5 (s2): W2 convert — overlaps ffn1
    split_w2<<<(C4W + 255) / 256, 256, 0, s2>>>(W2);
    cudaEventRecord(evW2, s2);

    // launch #6 (main): ffn2 (split-K=4, fused combine)
    cudaStreamWaitEvent(0, evW2, 0);
    {
        dim3 grid(D / 128, NMAX / 128, E * 4);      // 8 x 16 x 32
        ffn_mma<2, 4><<<grid, 256, SMEM_TOTAL>>>((const __half*)p_w2h, b2, out);
    }
    // launch #7 (main): finalize + self-clean
    finalize_kernel<<<1, 32>>>(out, N, (long long)out_size);
}